// round 10
// baseline (speedup 1.0000x reference)
#include <cuda_runtime.h>

#define NN 12288
#define EE 393216

// ---------------- scratch (device globals; no allocation allowed) ----------------
__device__ float g_dinv[NN];
__device__ int   g_deg[NN];
__device__ int   g_rowptr[NN + 1];
__device__ int   g_cursor[NN];
__device__ int   g_col[EE];
__device__ float g_pre[NN * 768];   // GEMM outputs (dinv-scaled), SpMM input
__device__ float g_post[NN * 768];  // SpMM output
__device__ float g_hs[NN * 64];
__device__ float g_xcf[NN * 256];
__device__ float g_bias[768];

// ---------------- graph preprocessing ----------------
__global__ void k_init() {
    int i = blockIdx.x * blockDim.x + threadIdx.x;
    if (i < NN) g_deg[i] = 1;  // self-loop
}

__global__ void k_count(const int* __restrict__ dst) {
    int e = blockIdx.x * blockDim.x + threadIdx.x;
    if (e < EE) atomicAdd(&g_deg[dst[e]], 1);
}

__global__ void k_dinv() {
    int i = blockIdx.x * blockDim.x + threadIdx.x;
    if (i < NN) g_dinv[i] = rsqrtf((float)g_deg[i]);
}

// single-block exclusive scan of (deg-1) over 12288 entries (1024 thr x 12)
__global__ void k_scan() {
    __shared__ int sums[1024];
    int t = threadIdx.x;
    int base = t * 12;
    int local[12];
    int s = 0;
#pragma unroll
    for (int i = 0; i < 12; i++) { local[i] = s; s += g_deg[base + i] - 1; }
    sums[t] = s;
    __syncthreads();
    for (int off = 1; off < 1024; off <<= 1) {
        int v = (t >= off) ? sums[t - off] : 0;
        __syncthreads();
        sums[t] += v;
        __syncthreads();
    }
    int pre = (t == 0) ? 0 : sums[t - 1];
#pragma unroll
    for (int i = 0; i < 12; i++) {
        int rp = pre + local[i];
        g_rowptr[base + i] = rp;
        g_cursor[base + i] = rp;
    }
    if (t == 1023) g_rowptr[NN] = sums[1023];
}

__global__ void k_scatter(const int* __restrict__ src, const int* __restrict__ dst) {
    int e = blockIdx.x * blockDim.x + threadIdx.x;
    if (e < EE) {
        int p = atomicAdd(&g_cursor[dst[e]], 1);
        g_col[p] = src[e];
    }
}

__global__ void k_xcf(const float* __restrict__ x) {
    int i = blockIdx.x * blockDim.x + threadIdx.x;
    if (i < NN * 256) {
        float v = x[i];
        if ((i & 255) == 0) v = 1.0f - v;
        g_xcf[i] = v;
    }
}

// ---------------- generic node GEMM: out[r, n0:n0+64] = dinv[r] * (A[r,:KIN] @ W) ----------------
// block = 64 rows x 64 cols, 256 threads, 4x4 micro-tile, K chunked by 32
template <int KIN>
__global__ void __launch_bounds__(256) k_gemm(const float* __restrict__ A, int lda,
                                              const float* __restrict__ W, int ldw,
                                              float* __restrict__ out, int ldo) {
    __shared__ float As[32 * 64];  // [k][m]
    __shared__ float Ws[32 * 64];  // [k][n]
    int tid = threadIdx.x;
    int tx = tid & 15, ty = tid >> 4;
    int m0 = blockIdx.x * 64;
    int n0 = blockIdx.y * 64;
    float acc[4][4] = {};
    for (int k0 = 0; k0 < KIN; k0 += 32) {
        {
            int m = tid >> 2;
            int kg = (tid & 3) * 8;
            const float4* ap = (const float4*)(A + (size_t)(m0 + m) * lda + k0 + kg);
            float4 v0 = ap[0], v1 = ap[1];
            As[(kg + 0) * 64 + m] = v0.x; As[(kg + 1) * 64 + m] = v0.y;
            As[(kg + 2) * 64 + m] = v0.z; As[(kg + 3) * 64 + m] = v0.w;
            As[(kg + 4) * 64 + m] = v1.x; As[(kg + 5) * 64 + m] = v1.y;
            As[(kg + 6) * 64 + m] = v1.z; As[(kg + 7) * 64 + m] = v1.w;
        }
        {
            int lin = tid * 8;
            int k = lin >> 6;
            int n = lin & 63;
            const float4* wp = (const float4*)(W + (size_t)(k0 + k) * ldw + n0 + n);
            float4 v0 = wp[0], v1 = wp[1];
            *(float4*)&Ws[k * 64 + n] = v0;
            *(float4*)&Ws[k * 64 + n + 4] = v1;
        }
        __syncthreads();
#pragma unroll
        for (int k = 0; k < 32; k++) {
            float4 a = *(float4*)&As[k * 64 + ty * 4];
            float4 b = *(float4*)&Ws[k * 64 + tx * 4];
            float av[4] = {a.x, a.y, a.z, a.w};
            float bv[4] = {b.x, b.y, b.z, b.w};
#pragma unroll
            for (int i = 0; i < 4; i++)
#pragma unroll
                for (int j = 0; j < 4; j++) acc[i][j] += av[i] * bv[j];
        }
        __syncthreads();
    }
#pragma unroll
    for (int i = 0; i < 4; i++) {
        int r = m0 + ty * 4 + i;
        float d = g_dinv[r];
        float4 v = make_float4(acc[i][0] * d, acc[i][1] * d, acc[i][2] * d, acc[i][3] * d);
        *(float4*)&out[(size_t)r * ldo + n0 + tx * 4] = v;
    }
}

// ---------------- SpMM: g_post[d,:] = relu?( dinv[d]*(self + sum_incoming g_pre[s,:]) + bias ) ----------------
template <int F>
__global__ void __launch_bounds__(128) k_spmm(int relu_upto) {
    constexpr int PF = F / 128;
    __shared__ int scol[128];
    int d = blockIdx.x, t = threadIdx.x;
    float acc[PF];
#pragma unroll
    for (int j = 0; j < PF; j++) acc[j] = g_pre[(size_t)d * F + j * 128 + t];  // self-loop
    int beg = g_rowptr[d], end = g_rowptr[d + 1];
    for (int base = beg; base < end; base += 128) {
        int cnt = min(128, end - base);
        if (t < cnt) scol[t] = g_col[base + t];
        __syncthreads();
        for (int e = 0; e < cnt; e++) {
            const float* gr = &g_pre[(size_t)scol[e] * F];
#pragma unroll
            for (int j = 0; j < PF; j++) acc[j] += gr[j * 128 + t];
        }
        __syncthreads();
    }
    float dv = g_dinv[d];
#pragma unroll
    for (int j = 0; j < PF; j++) {
        int c = j * 128 + t;
        float v = acc[j] * dv + g_bias[c];
        if (c < relu_upto) v = fmaxf(v, 0.0f);
        g_post[(size_t)d * F + c] = v;
    }
}

// ---------------- output splits ----------------
__global__ void k_split_z(float* __restrict__ out) {
    int i = blockIdx.x * blockDim.x + threadIdx.x;
    if (i < NN * 64) {
        int r = i >> 6, c = i & 63;
        float v = g_post[r * 128 + c];
        if (c < 32) out[r * 32 + c] = v;
        else out[NN * 32 + r * 32 + (c - 32)] = v;
    }
}

__global__ void k_copy_hs() {
    int i = blockIdx.x * blockDim.x + threadIdx.x;
    if (i < NN * 64) {
        int r = i >> 6, c = i & 63;
        g_hs[i] = g_post[r * 256 + 192 + c];
    }
}

__global__ void k_split_dec(float* __restrict__ out) {
    int i = blockIdx.x * blockDim.x + threadIdx.x;
    if (i < NN * 768) {
        int r = i / 768, c = i % 768;
        int seg = c >> 8, cc = c & 255;
        out[(size_t)seg * NN * 256 + (size_t)r * 256 + cc] = g_post[i];
    }
}

// ---------------- SYRK: C = hs @ hs^T, symmetric, 128x128 tiles ----------------
__global__ void __launch_bounds__(256) k_syrk(float* __restrict__ C) {
    __shared__ float sm[8192];  // phase A: sA(128x32)+sB(128x32); phase B: 64x128 transpose stage
    int bx = blockIdx.x, by = blockIdx.y;
    if (by > bx) return;
    int tid = threadIdx.x;
    int tx = tid & 15, ty = tid >> 4;
    float* sA = sm;
    float* sB = sm + 4096;
    float acc[8][8] = {};
    for (int k0 = 0; k0 < 64; k0 += 32) {
#pragma unroll
        for (int i = 0; i < 4; i++) {
            int f4 = tid * 4 + i;       // 1024 float4 per tile
            int m = f4 >> 3, kq = f4 & 7;
            float4 va = *(const float4*)&g_hs[(size_t)(bx * 128 + m) * 64 + k0 + kq * 4];
            sA[(kq * 4 + 0) * 128 + m] = va.x; sA[(kq * 4 + 1) * 128 + m] = va.y;
            sA[(kq * 4 + 2) * 128 + m] = va.z; sA[(kq * 4 + 3) * 128 + m] = va.w;
            float4 vb = *(const float4*)&g_hs[(size_t)(by * 128 + m) * 64 + k0 + kq * 4];
            sB[(kq * 4 + 0) * 128 + m] = vb.x; sB[(kq * 4 + 1) * 128 + m] = vb.y;
            sB[(kq * 4 + 2) * 128 + m] = vb.z; sB[(kq * 4 + 3) * 128 + m] = vb.w;
        }
        __syncthreads();
#pragma unroll
        for (int k = 0; k < 32; k++) {
            float4 a0 = *(float4*)&sA[k * 128 + ty * 8];
            float4 a1 = *(float4*)&sA[k * 128 + ty * 8 + 4];
            float4 b0 = *(float4*)&sB[k * 128 + tx * 8];
            float4 b1 = *(float4*)&sB[k * 128 + tx * 8 + 4];
            float av[8] = {a0.x, a0.y, a0.z, a0.w, a1.x, a1.y, a1.z, a1.w};
            float bv[8] = {b0.x, b0.y, b0.z, b0.w, b1.x, b1.y, b1.z, b1.w};
#pragma unroll
            for (int i = 0; i < 8; i++)
#pragma unroll
                for (int j = 0; j < 8; j++) acc[i][j] += av[i] * bv[j];
        }
        __syncthreads();
    }
    // direct tile write (coalesced)
#pragma unroll
    for (int i = 0; i < 8; i++) {
        size_t r = (size_t)(bx * 128 + ty * 8 + i) * NN + by * 128 + tx * 8;
        float4 v0 = make_float4(acc[i][0], acc[i][1], acc[i][2], acc[i][3]);
        float4 v1 = make_float4(acc[i][4], acc[i][5], acc[i][6], acc[i][7]);
        *(float4*)&C[r] = v0;
        *(float4*)&C[r + 4] = v1;
    }
    // mirror tile via smem transpose (two 64-row halves, writes stay coalesced)
    if (bx != by) {
#pragma unroll
        for (int h = 0; h < 2; h++) {
            __syncthreads();
            if ((tx >> 3) == h) {
                int txl = tx & 7;
#pragma unroll
                for (int j = 0; j < 8; j++)
#pragma unroll
                    for (int i = 0; i < 8; i++)
                        sm[(txl * 8 + j) * 128 + ty * 8 + i] = acc[i][j];
            }
            __syncthreads();
            int rrl = tid >> 2;
            int c0 = (tid & 3) * 32;
            const float* s = &sm[rrl * 128 + c0];
            float* dstp = &C[(size_t)(by * 128 + h * 64 + rrl) * NN + bx * 128 + c0];
#pragma unroll
            for (int q = 0; q < 8; q++) ((float4*)dstp)[q] = ((const float4*)s)[q];
        }
    }
}

// ---------------- launch ----------------
extern "C" void kernel_launch(void* const* d_in, const int* in_sizes, int n_in,
                              void* d_out, int out_size) {
    const float* x = (const float*)d_in[0];
    const int* ei = (const int*)d_in[1];
    const int* src = ei;
    const int* dst = ei + EE;
    const float* enc_W1 = (const float*)d_in[2];
    const float* enc_b1 = (const float*)d_in[3];
    const float* enc_W2 = (const float*)d_in[4];
    const float* enc_b2 = (const float*)d_in[5];
    const float* d1_W1 = (const float*)d_in[6];
    const float* d1_b1 = (const float*)d_in[7];
    const float* d1_W2 = (const float*)d_in[8];
    const float* d1_b2 = (const float*)d_in[9];
    const float* d2_W1 = (const float*)d_in[10];
    const float* d2_b1 = (const float*)d_in[11];
    const float* d2_W2 = (const float*)d_in[12];
    const float* d2_b2 = (const float*)d_in[13];
    const float* s_W = (const float*)d_in[14];
    const float* s_b = (const float*)d_in[15];
    float* out = (float*)d_out;

    float *pre, *post, *xcf;
    cudaGetSymbolAddress((void**)&pre, g_pre);
    cudaGetSymbolAddress((void**)&post, g_post);
    cudaGetSymbolAddress((void**)&xcf, g_xcf);

    // graph preprocessing (CSR over incoming edges, self-loops implicit)
    k_init<<<48, 256>>>();
    k_count<<<EE / 256, 256>>>(dst);
    k_dinv<<<48, 256>>>();
    k_scan<<<1, 1024>>>();
    k_scatter<<<EE / 256, 256>>>(src, dst);
    k_xcf<<<NN * 256 / 256, 256>>>(x);

    // stage 1: encoder layer 1 on [x | x_cf]  (128 cols), relu
    k_gemm<256><<<dim3(192, 1), 256>>>(x, 256, enc_W1, 64, pre, 128);
    k_gemm<256><<<dim3(192, 1), 256>>>(xcf, 256, enc_W1, 64, pre + 64, 128);
    cudaMemcpyToSymbolAsync(g_bias, enc_b1, 256, 0, cudaMemcpyDeviceToDevice, 0);
    cudaMemcpyToSymbolAsync(g_bias, enc_b1, 256, 256, cudaMemcpyDeviceToDevice, 0);
    k_spmm<128><<<NN, 128>>>(128);

    // stage 2: encoder layer 2 -> z | z_cf, no relu
    k_gemm<64><<<dim3(192, 1), 256>>>(post, 128, enc_W2, 64, pre, 128);
    k_gemm<64><<<dim3(192, 1), 256>>>(post + 64, 128, enc_W2, 64, pre + 64, 128);
    cudaMemcpyToSymbolAsync(g_bias, enc_b2, 256, 0, cudaMemcpyDeviceToDevice, 0);
    cudaMemcpyToSymbolAsync(g_bias, enc_b2, 256, 256, cudaMemcpyDeviceToDevice, 0);
    k_spmm<128><<<NN, 128>>>(0);

    k_split_z<<<NN * 64 / 256, 256>>>(out);

    // stage 3: dec1(z_s) L1 | dec2(z_ns) L1 | dec1(z_s_cf) L1 | s-conv(z_ns)  (256 cols)
    k_gemm<32><<<dim3(192, 1), 256>>>(post, 128, d1_W1, 64, pre, 256);
    k_gemm<32><<<dim3(192, 1), 256>>>(post + 32, 128, d2_W1, 64, pre + 64, 256);
    k_gemm<32><<<dim3(192, 1), 256>>>(post + 64, 128, d1_W1, 64, pre + 128, 256);
    k_gemm<32><<<dim3(192, 1), 256>>>(post + 32, 128, s_W, 64, pre + 192, 256);
    cudaMemcpyToSymbolAsync(g_bias, d1_b1, 256, 0, cudaMemcpyDeviceToDevice, 0);
    cudaMemcpyToSymbolAsync(g_bias, d2_b1, 256, 256, cudaMemcpyDeviceToDevice, 0);
    cudaMemcpyToSymbolAsync(g_bias, d1_b1, 256, 512, cudaMemcpyDeviceToDevice, 0);
    cudaMemcpyToSymbolAsync(g_bias, s_b, 256, 768, cudaMemcpyDeviceToDevice, 0);
    k_spmm<256><<<NN, 128>>>(192);  // relu on first 3 segments; hs (cols 192..255) raw

    k_copy_hs<<<NN * 64 / 256, 256>>>();

    // stage 4: decoders layer 2 (768 cols), no relu
    k_gemm<64><<<dim3(192, 4), 256>>>(post, 256, d1_W2, 256, pre, 768);
    k_gemm<64><<<dim3(192, 4), 256>>>(post + 64, 256, d2_W2, 256, pre + 256, 768);
    k_gemm<64><<<dim3(192, 4), 256>>>(post + 128, 256, d1_W2, 256, pre + 512, 768);
    cudaMemcpyToSymbolAsync(g_bias, d1_b2, 1024, 0, cudaMemcpyDeviceToDevice, 0);
    cudaMemcpyToSymbolAsync(g_bias, d2_b2, 1024, 1024, cudaMemcpyDeviceToDevice, 0);
    cudaMemcpyToSymbolAsync(g_bias, d1_b2, 1024, 2048, cudaMemcpyDeviceToDevice, 0);
    k_spmm<768><<<NN, 128>>>(0);

    k_split_dec<<<NN * 768 / 256, 256>>>(out + NN * 64);

    // stage 5: s_ = hs @ hs^T (symmetric)
    k_syrk<<<dim3(96, 96), 256>>>(out + (size_t)NN * 64 + (size_t)3 * NN * 256);
}

// round 13
// speedup vs baseline: 1.0191x; 1.0191x over previous
#include <cuda_runtime.h>

#define NN 12288
#define EE 393216

#define FFMA2(d, a, b) asm("fma.rn.f32x2 %0, %1, %2, %0;" : "+l"(d) : "l"(a), "l"(b))

// ---------------- scratch (device globals; no allocation allowed) ----------------
__device__ float g_dinv[NN];
__device__ int   g_deg[NN];
__device__ int   g_rowptr[NN + 1];
__device__ int   g_cursor[NN];
__device__ int   g_col[EE];
__device__ float g_pre[NN * 256];   // SpMM input (dinv-pre-scaled)
__device__ float g_post[NN * 256];  // SpMM output
__device__ float g_hs[NN * 64];
__device__ float g_xcf[NN * 256];
__device__ float g_bias[256];

// ---------------- graph preprocessing ----------------
__global__ void k_init() {
    int i = blockIdx.x * blockDim.x + threadIdx.x;
    if (i < NN) g_deg[i] = 1;  // self-loop
}

__global__ void k_count(const int* __restrict__ dst) {
    int e = blockIdx.x * blockDim.x + threadIdx.x;
    if (e < EE) atomicAdd(&g_deg[dst[e]], 1);
}

__global__ void k_dinv() {
    int i = blockIdx.x * blockDim.x + threadIdx.x;
    if (i < NN) g_dinv[i] = rsqrtf((float)g_deg[i]);
}

// shuffle-based exclusive scan of (deg-1) over 12288 entries
__global__ void k_scan() {
    __shared__ int wsum[32];
    int t = threadIdx.x;  // 1024
    int lane = t & 31, warp = t >> 5;
    int base = t * 12;
    int local[12];
    int s = 0;
#pragma unroll
    for (int i = 0; i < 12; i++) { local[i] = s; s += g_deg[base + i] - 1; }
    int v = s;
#pragma unroll
    for (int o = 1; o < 32; o <<= 1) { int u = __shfl_up_sync(~0u, v, o); if (lane >= o) v += u; }
    if (lane == 31) wsum[warp] = v;
    __syncthreads();
    if (warp == 0) {
        int w = wsum[lane];
#pragma unroll
        for (int o = 1; o < 32; o <<= 1) { int u = __shfl_up_sync(~0u, w, o); if (lane >= o) w += u; }
        wsum[lane] = w;
    }
    __syncthreads();
    int pre = v - s + (warp ? wsum[warp - 1] : 0);
#pragma unroll
    for (int i = 0; i < 12; i++) {
        int rp = pre + local[i];
        g_rowptr[base + i] = rp;
        g_cursor[base + i] = rp;
    }
    if (t == 1023) g_rowptr[NN] = pre + s;
}

__global__ void k_scatter(const int* __restrict__ src, const int* __restrict__ dst) {
    int e = blockIdx.x * blockDim.x + threadIdx.x;
    if (e < EE) {
        int p = atomicAdd(&g_cursor[dst[e]], 1);
        g_col[p] = src[e];
    }
}

__global__ void k_xcf(const float* __restrict__ x) {
    int i = blockIdx.x * blockDim.x + threadIdx.x;
    if (i < NN * 256) {
        float v = x[i];
        if ((i & 255) == 0) v = 1.0f - v;
        g_xcf[i] = v;
    }
}

// scale a 128-col block by dinv[row]: pre = dinv * post
__global__ void k_prescale128() {
    int i = blockIdx.x * blockDim.x + threadIdx.x;
    if (i < NN * 128) g_pre[i] = g_post[i] * g_dinv[i >> 7];
}

// ---------------- generic node GEMM (f32x2 packed): out = f(A@W) ----------------
// block = 64 rows x 64 cols, 256 threads, 4x4 micro-tile (packed as 4x2 f32x2 pairs)
// flags: bit0 = relu, bit1 = scale by dinv[row]. bias may be null.
template <int KIN>
__global__ void __launch_bounds__(256) k_gemm(const float* __restrict__ A, int lda,
                                              const float* __restrict__ W, int ldw,
                                              const float* __restrict__ bias,
                                              float* __restrict__ out, int ldo, int flags) {
    __shared__ float sA[32 * 128];  // [k][2m] duplicated pairs (a,a)
    __shared__ float sB[32 * 64];   // [k][n]
    int tid = threadIdx.x;
    int tx = tid & 15, ty = tid >> 4;
    int m0 = blockIdx.x * 64;
    int n0 = blockIdx.y * 64;
    unsigned long long acc2[4][2] = {};
    for (int k0 = 0; k0 < KIN; k0 += 32) {
        {
            int m = tid >> 2;
            int kg = (tid & 3) * 8;
            const float4* ap = (const float4*)(A + (size_t)(m0 + m) * lda + k0 + kg);
            float4 v0 = ap[0], v1 = ap[1];
            float2* r0 = (float2*)&sA[(kg + 0) * 128];
            float2* r1 = (float2*)&sA[(kg + 1) * 128];
            float2* r2 = (float2*)&sA[(kg + 2) * 128];
            float2* r3 = (float2*)&sA[(kg + 3) * 128];
            float2* r4 = (float2*)&sA[(kg + 4) * 128];
            float2* r5 = (float2*)&sA[(kg + 5) * 128];
            float2* r6 = (float2*)&sA[(kg + 6) * 128];
            float2* r7 = (float2*)&sA[(kg + 7) * 128];
            r0[m] = make_float2(v0.x, v0.x); r1[m] = make_float2(v0.y, v0.y);
            r2[m] = make_float2(v0.z, v0.z); r3[m] = make_float2(v0.w, v0.w);
            r4[m] = make_float2(v1.x, v1.x); r5[m] = make_float2(v1.y, v1.y);
            r6[m] = make_float2(v1.z, v1.z); r7[m] = make_float2(v1.w, v1.w);
        }
        {
            int lin = tid * 8;
            int k = lin >> 6;
            int n = lin & 63;
            const float4* wp = (const float4*)(W + (size_t)(k0 + k) * ldw + n0 + n);
            float4 v0 = wp[0], v1 = wp[1];
            *(float4*)&sB[k * 64 + n] = v0;
            *(float4*)&sB[k * 64 + n + 4] = v1;
        }
        __syncthreads();
#pragma unroll
        for (int k = 0; k < 32; k++) {
            ulonglong2 a0 = *(ulonglong2*)&sA[k * 128 + ty * 8];
            ulonglong2 a1 = *(ulonglong2*)&sA[k * 128 + ty * 8 + 4];
            ulonglong2 b0 = *(ulonglong2*)&sB[k * 64 + tx * 4];
            unsigned long long av[4] = {a0.x, a0.y, a1.x, a1.y};
            unsigned long long bv[2] = {b0.x, b0.y};
#pragma unroll
            for (int i = 0; i < 4; i++) {
                FFMA2(acc2[i][0], av[i], bv[0]);
                FFMA2(acc2[i][1], av[i], bv[1]);
            }
        }
        __syncthreads();
    }
    float(*accf)[4] = (float(*)[4])acc2;
    float bb[4] = {0.f, 0.f, 0.f, 0.f};
    if (bias) {
        float4 b4 = *(const float4*)&bias[n0 + tx * 4];
        bb[0] = b4.x; bb[1] = b4.y; bb[2] = b4.z; bb[3] = b4.w;
    }
#pragma unroll
    for (int i = 0; i < 4; i++) {
        int r = m0 + ty * 4 + i;
        float d = (flags & 2) ? g_dinv[r] : 1.0f;
        float v[4];
#pragma unroll
        for (int j = 0; j < 4; j++) {
            float t = accf[i][j] + bb[j];
            if (flags & 1) t = fmaxf(t, 0.0f);
            v[j] = t * d;
        }
        *(float4*)&out[(size_t)r * ldo + n0 + tx * 4] = make_float4(v[0], v[1], v[2], v[3]);
    }
}

// ---------------- SpMM: g_post[d,:] = relu?( dinv[d]*(self + sum_in g_pre[s,:]) [+ bias] ) ----------------
template <int F, int T, bool BIAS>
__global__ void __launch_bounds__(T) k_spmm(int relu_upto) {
    constexpr int PF = F / T;
    __shared__ int scol[T];
    int d = blockIdx.x, t = threadIdx.x;
    float acc[PF];
#pragma unroll
    for (int j = 0; j < PF; j++) acc[j] = g_pre[(size_t)d * F + j * T + t];  // self-loop
    int beg = g_rowptr[d], end = g_rowptr[d + 1];
    for (int base = beg; base < end; base += T) {
        int cnt = min(T, end - base);
        if (t < cnt) scol[t] = g_col[base + t];
        __syncthreads();
        for (int e = 0; e < cnt; e++) {
            const float* gr = &g_pre[(size_t)scol[e] * F];
#pragma unroll
            for (int j = 0; j < PF; j++) acc[j] += gr[j * T + t];
        }
        __syncthreads();
    }
    float dv = g_dinv[d];
#pragma unroll
    for (int j = 0; j < PF; j++) {
        int c = j * T + t;
        float v = acc[j] * dv;
        if (BIAS) v += g_bias[c];
        if (c < relu_upto) v = fmaxf(v, 0.0f);
        g_post[(size_t)d * F + c] = v;
    }
}

// ---------------- output split for z ----------------
__global__ void k_split_z(float* __restrict__ out) {
    int i = blockIdx.x * blockDim.x + threadIdx.x;
    if (i < NN * 64) {
        int r = i >> 6, c = i & 63;
        float v = g_post[r * 128 + c];
        if (c < 32) out[r * 32 + c] = v;
        else out[NN * 32 + r * 32 + (c - 32)] = v;
    }
}

// ---------------- SYRK: C = hs @ hs^T, symmetric, 128x128 tiles, f32x2 packed ----------------
__global__ void __launch_bounds__(256) k_syrk(float* __restrict__ C) {
    __shared__ float sm[32 * 256 + 32 * 128];  // sA_dup 8192 + sB 4096 floats (48KB)
    int bx = blockIdx.x, by = blockIdx.y;
    if (by > bx) return;
    int tid = threadIdx.x;
    int tx = tid & 15, ty = tid >> 4;
    float* sA = sm;         // [k][2m] dup pairs, 32 x 256
    float* sB = sm + 8192;  // [k][n], 32 x 128
    unsigned long long acc2[8][4] = {};
    for (int k0 = 0; k0 < 64; k0 += 32) {
#pragma unroll
        for (int i = 0; i < 4; i++) {
            int f4 = tid * 4 + i;  // 1024 float4 per tile
            int m = f4 >> 3, kq = f4 & 7;
            float4 va = *(const float4*)&g_hs[(size_t)(bx * 128 + m) * 64 + k0 + kq * 4];
            ((float2*)&sA[(kq * 4 + 0) * 256])[m] = make_float2(va.x, va.x);
            ((float2*)&sA[(kq * 4 + 1) * 256])[m] = make_float2(va.y, va.y);
            ((float2*)&sA[(kq * 4 + 2) * 256])[m] = make_float2(va.z, va.z);
            ((float2*)&sA[(kq * 4 + 3) * 256])[m] = make_float2(va.w, va.w);
            float4 vb = *(const float4*)&g_hs[(size_t)(by * 128 + m) * 64 + k0 + kq * 4];
            sB[(kq * 4 + 0) * 128 + m] = vb.x; sB[(kq * 4 + 1) * 128 + m] = vb.y;
            sB[(kq * 4 + 2) * 128 + m] = vb.z; sB[(kq * 4 + 3) * 128 + m] = vb.w;
        }
        __syncthreads();
#pragma unroll
        for (int k = 0; k < 32; k++) {
            ulonglong2 a0 = *(ulonglong2*)&sA[k * 256 + ty * 16];
            ulonglong2 a1 = *(ulonglong2*)&sA[k * 256 + ty * 16 + 4];
            ulonglong2 a2 = *(ulonglong2*)&sA[k * 256 + ty * 16 + 8];
            ulonglong2 a3 = *(ulonglong2*)&sA[k * 256 + ty * 16 + 12];
            ulonglong2 b0 = *(ulonglong2*)&sB[k * 128 + tx * 8];
            ulonglong2 b1 = *(ulonglong2*)&sB[k * 128 + tx * 8 + 4];
            unsigned long long av[8] = {a0.x, a0.y, a1.x, a1.y, a2.x, a2.y, a3.x, a3.y};
            unsigned long long bv[4] = {b0.x, b0.y, b1.x, b1.y};
#pragma unroll
            for (int i = 0; i < 8; i++) {
#pragma unroll
                for (int j = 0; j < 4; j++) FFMA2(acc2[i][j], av[i], bv[j]);
            }
        }
        __syncthreads();
    }
    float(*accf)[8] = (float(*)[8])acc2;
    // direct tile write (coalesced)
#pragma unroll
    for (int i = 0; i < 8; i++) {
        size_t r = (size_t)(bx * 128 + ty * 8 + i) * NN + by * 128 + tx * 8;
        *(float4*)&C[r] = make_float4(accf[i][0], accf[i][1], accf[i][2], accf[i][3]);
        *(float4*)&C[r + 4] = make_float4(accf[i][4], accf[i][5], accf[i][6], accf[i][7]);
    }
    // mirror tile via smem transpose (two 64-row halves, writes stay coalesced)
    if (bx != by) {
#pragma unroll
        for (int h = 0; h < 2; h++) {
            __syncthreads();
            if ((tx >> 3) == h) {
                int txl = tx & 7;
#pragma unroll
                for (int j = 0; j < 8; j++)
#pragma unroll
                    for (int i = 0; i < 8; i++)
                        sm[(txl * 8 + j) * 128 + ty * 8 + i] = accf[i][j];
            }
            __syncthreads();
            int rrl = tid >> 2;
            int c0 = (tid & 3) * 32;
            const float* s = &sm[rrl * 128 + c0];
            float* dstp = &C[(size_t)(by * 128 + h * 64 + rrl) * NN + bx * 128 + c0];
#pragma unroll
            for (int q = 0; q < 8; q++) ((float4*)dstp)[q] = ((const float4*)s)[q];
        }
    }
}

// ---------------- launch ----------------
extern "C" void kernel_launch(void* const* d_in, const int* in_sizes, int n_in,
                              void* d_out, int out_size) {
    const float* x = (const float*)d_in[0];
    const int* ei = (const int*)d_in[1];
    const int* src = ei;
    const int* dst = ei + EE;
    const float* enc_W1 = (const float*)d_in[2];
    const float* enc_b1 = (const float*)d_in[3];
    const float* enc_W2 = (const float*)d_in[4];
    const float* enc_b2 = (const float*)d_in[5];
    const float* d1_W1 = (const float*)d_in[6];
    const float* d1_b1 = (const float*)d_in[7];
    const float* d1_W2 = (const float*)d_in[8];
    const float* d1_b2 = (const float*)d_in[9];
    const float* d2_W1 = (const float*)d_in[10];
    const float* d2_b1 = (const float*)d_in[11];
    const float* d2_W2 = (const float*)d_in[12];
    const float* d2_b2 = (const float*)d_in[13];
    const float* s_W = (const float*)d_in[14];
    const float* s_b = (const float*)d_in[15];
    float* out = (float*)d_out;

    float *pre, *post, *xcf, *hs;
    cudaGetSymbolAddress((void**)&pre, g_pre);
    cudaGetSymbolAddress((void**)&post, g_post);
    cudaGetSymbolAddress((void**)&xcf, g_xcf);
    cudaGetSymbolAddress((void**)&hs, g_hs);

    // graph preprocessing (CSR over incoming edges, self-loops implicit)
    k_init<<<48, 256>>>();
    k_count<<<EE / 256, 256>>>(dst);
    k_dinv<<<48, 256>>>();
    k_scan<<<1, 1024>>>();
    k_scatter<<<EE / 256, 256>>>(src, dst);
    k_xcf<<<NN * 256 / 256, 256>>>(x);

    // stage 1: encoder layer 1 on [x | x_cf]  (128 cols), bias + relu in SpMM
    k_gemm<256><<<dim3(192, 1), 256>>>(x, 256, enc_W1, 64, nullptr, pre, 128, 2);
    k_gemm<256><<<dim3(192, 1), 256>>>(xcf, 256, enc_W1, 64, nullptr, pre + 64, 128, 2);
    cudaMemcpyToSymbolAsync(g_bias, enc_b1, 256, 0, cudaMemcpyDeviceToDevice, 0);
    cudaMemcpyToSymbolAsync(g_bias, enc_b1, 256, 256, cudaMemcpyDeviceToDevice, 0);
    k_spmm<128, 128, true><<<NN, 128>>>(128);

    // stage 2: encoder layer 2 -> z | z_cf, bias, no relu
    k_gemm<64><<<dim3(192, 1), 256>>>(post, 128, enc_W2, 64, nullptr, pre, 128, 2);
    k_gemm<64><<<dim3(192, 1), 256>>>(post + 64, 128, enc_W2, 64, nullptr, pre + 64, 128, 2);
    cudaMemcpyToSymbolAsync(g_bias, enc_b2, 256, 0, cudaMemcpyDeviceToDevice, 0);
    cudaMemcpyToSymbolAsync(g_bias, enc_b2, 256, 256, cudaMemcpyDeviceToDevice, 0);
    k_spmm<128, 128, true><<<NN, 128>>>(0);

    k_split_z<<<NN * 64 / 256, 256>>>(out);

    // stage 3 restructured: aggregate z FIRST (A(hW) == (Ah)W), then small GEMMs.
    // aggZ = A_hat @ [z | z_cf]  (128 cols)
    k_prescale128<<<NN * 128 / 256, 256>>>();
    k_spmm<128, 128, false><<<NN, 128>>>(0);
    // h1 = dinv * relu(aggZ_seg @ W1 + b1)   (pre-scaled for the NEXT aggregation)
    k_gemm<32><<<dim3(192, 1), 256>>>(post, 128, d1_W1, 64, d1_b1, pre, 192, 3);
    k_gemm<32><<<dim3(192, 1), 256>>>(post + 32, 128, d2_W1, 64, d2_b1, pre + 64, 192, 3);
    k_gemm<32><<<dim3(192, 1), 256>>>(post + 64, 128, d1_W1, 64, d1_b1, pre + 128, 192, 3);
    // hs = aggZ_ns @ s_W + s_b  (conv output directly; no relu, no scale)
    k_gemm<32><<<dim3(192, 1), 256>>>(post + 32, 128, s_W, 64, s_b, hs, 64, 0);

    // stage 4 restructured: aggregate the 192-col hidden, then GEMM straight into out
    k_spmm<192, 64, false><<<NN, 64>>>(0);
    k_gemm<64><<<dim3(192, 4), 256>>>(post, 192, d1_W2, 256, d1_b2, out + NN * 64, 256, 0);
    k_gemm<64><<<dim3(192, 4), 256>>>(post + 64, 192, d2_W2, 256, d2_b2, out + NN * 64 + (size_t)NN * 256, 256, 0);
    k_gemm<64><<<dim3(192, 4), 256>>>(post + 128, 192, d1_W2, 256, d1_b2, out + NN * 64 + (size_t)2 * NN * 256, 256, 0);

    // stage 5: s_ = hs @ hs^T (symmetric)
    k_syrk<<<dim3(96, 96), 256>>>(out + (size_t)NN * 64 + (size_t)3 * NN * 256);
}